// round 8
// baseline (speedup 1.0000x reference)
#include <cuda_runtime.h>

// StackedLSTM: B=2048, T=2048, D=H=6, 2 layers, softmax over final h of layer 1.
// 16 lanes per batch: lanes 0-7 run layer 0 (unit j = lane&7), lanes 8-15 layer 1
// (1-step skew). State exchange is pure register shuffles (12 shfl.sync/iter,
// per-lane source indices; no smem, no syncwarp). f32x2 FFMA with k-pair packing;
// weights in registers with sigmoid 0.5-prescale folded in. x double-buffered.

#define TT 2048

typedef unsigned long long u64;
typedef ulonglong2 u64x2;

__device__ __forceinline__ u64 pack2(float lo, float hi) {
    u64 r; asm("mov.b64 %0, {%1, %2};" : "=l"(r) : "f"(lo), "f"(hi)); return r;
}
__device__ __forceinline__ void unpack2(u64 v, float& lo, float& hi) {
    asm("mov.b64 {%0, %1}, %2;" : "=f"(lo), "=f"(hi) : "l"(v));
}
__device__ __forceinline__ u64 ffma2(u64 a, u64 b, u64 c) {
    u64 d; asm("fma.rn.f32x2 %0, %1, %2, %3;" : "=l"(d) : "l"(a), "l"(b), "l"(c));
    return d;
}
__device__ __forceinline__ u64 fadd2(u64 a, u64 b) {
    u64 d; asm("add.rn.f32x2 %0, %1, %2;" : "=l"(d) : "l"(a), "l"(b)); return d;
}
__device__ __forceinline__ float tanh_f(float x) {
    float y; asm("tanh.approx.f32 %0, %1;" : "=f"(y) : "f"(x)); return y;
}

struct CellW {
    u64 wx[4][3];   // input-side weight k-pairs per gate (i,f,g,o), prescaled
    u64 wh[4][3];   // recurrent-side weight k-pairs
    u64 b[4];       // bias in lo half, 0 in hi half
};

// One LSTM cell: in[3]/rg[3] are k-pair packed {v2k, v2k+1} input/recurrent vecs.
__device__ __forceinline__ void cell(const CellW& W, const u64* in, const u64* rg,
                                     float& h, float& c) {
    float g[4];
#pragma unroll
    for (int q = 0; q < 4; ++q) {
        u64 ax = ffma2(W.wx[q][0], in[0], W.b[q]);
        ax     = ffma2(W.wx[q][1], in[1], ax);
        ax     = ffma2(W.wx[q][2], in[2], ax);
        u64 ah = ffma2(W.wh[q][0], rg[0], 0ull);
        ah     = ffma2(W.wh[q][1], rg[1], ah);
        ah     = ffma2(W.wh[q][2], rg[2], ah);
        u64 s2 = fadd2(ax, ah);
        float lo, hi; unpack2(s2, lo, hi);
        g[q] = lo + hi;
    }
    // sigmoid gates were prescaled by 0.5 in the weights: sig = .5 + .5*tanh(g^)
    float gi = fmaf(tanh_f(g[0]), 0.5f, 0.5f);
    float gf = fmaf(tanh_f(g[1]), 0.5f, 0.5f);
    float gg = tanh_f(g[2]);
    float go = fmaf(tanh_f(g[3]), 0.5f, 0.5f);
    c = fmaf(gf, c, gi * gg);
    h = go * tanh_f(c);
}

// One fused iteration: 12 shuffles broadcast state, lanes select input
// (x for L0, h0 for L1), one cell. No smem, no explicit sync.
template <bool ZF>
__device__ __forceinline__ void iter(const CellW& W, bool isL1,
                                     int rbase, int gbase,
                                     const u64* xp, float& h, float& c) {
    float r[6], a[6];
#pragma unroll
    for (int k = 0; k < 6; ++k)
        r[k] = __shfl_sync(0xffffffffu, h, rbase + k);   // own-layer recurrence
#pragma unroll
    for (int k = 0; k < 6; ++k)
        a[k] = __shfl_sync(0xffffffffu, h, gbase + k);   // h0 (L1 input)
    u64 rg[3] = { pack2(r[0], r[1]), pack2(r[2], r[3]), pack2(r[4], r[5]) };
    u64 hv[3] = { pack2(a[0], a[1]), pack2(a[2], a[3]), pack2(a[4], a[5]) };
    u64 in[3] = { isL1 ? hv[0] : xp[0], isL1 ? hv[1] : xp[1], isL1 ? hv[2] : xp[2] };
    cell(W, in, rg, h, c);
    if (ZF && isL1) { h = 0.f; c = 0.f; }   // iteration 0: layer-1 step is spurious
}

// 4 timesteps from one x block (12 u64 = 24 floats).
template <bool ZF>
__device__ __forceinline__ void steps4(const CellW& W, bool isL1,
                                       int rbase, int gbase,
                                       const u64* u, float& h, float& c) {
    iter<ZF>   (W, isL1, rbase, gbase, u + 0, h, c);
    iter<false>(W, isL1, rbase, gbase, u + 3, h, c);
    iter<false>(W, isL1, rbase, gbase, u + 6, h, c);
    iter<false>(W, isL1, rbase, gbase, u + 9, h, c);
}

__device__ __forceinline__ void loadblk(const float* __restrict__ xb, int m, u64* u) {
    const u64x2* p = (const u64x2*)(xb + 24 * m);   // 96B block, 16B aligned
#pragma unroll
    for (int i = 0; i < 6; ++i) { u64x2 v = p[i]; u[2 * i] = v.x; u[2 * i + 1] = v.y; }
}

__global__ void __launch_bounds__(256, 1)
stacked_lstm_kernel(const float* __restrict__ x,
                    const float* __restrict__ Wi0, const float* __restrict__ Wh0,
                    const float* __restrict__ bi0, const float* __restrict__ bh0,
                    const float* __restrict__ Wi1, const float* __restrict__ Wh1,
                    const float* __restrict__ bi1, const float* __restrict__ bh1,
                    float* __restrict__ out) {
    const int lane  = threadIdx.x & 31;
    const bool isL1 = (lane & 8) != 0;      // lanes 8-15 / 24-31 run layer 1
    const int j     = lane & 7;             // hidden unit (6,7 idle padding lanes)
    const int jj    = (j < 6) ? j : 5;      // clamp for safe weight loads
    const int gbase = lane & ~15;           // group base = layer-0 lanes
    const int rbase = isL1 ? gbase + 8 : gbase;   // own-layer shuffle base
    const int b     = (blockIdx.x * blockDim.x + threadIdx.x) >> 4;   // batch

    // Per-lane weight set.
    const float* Wi = isL1 ? Wi1 : Wi0;
    const float* Wh = isL1 ? Wh1 : Wh0;
    const float* bi = isL1 ? bi1 : bi0;
    const float* bh = isL1 ? bh1 : bh0;

    // PyTorch gate rows: i=[0:6) f=[6:12) g=[12:18) o=[18:24).
    // Sigmoid gates (i,f,o) prescaled by 0.5 so sig = .5 + .5*tanh(prescaled).
    CellW W;
    const int   goff[4] = {0, 6, 12, 18};
    const float gscl[4] = {0.5f, 0.5f, 1.0f, 0.5f};
#pragma unroll
    for (int q = 0; q < 4; ++q) {
        const int   r = goff[q] + jj;
        const float s = gscl[q];
#pragma unroll
        for (int p = 0; p < 3; ++p) {
            W.wx[q][p] = pack2(s * Wi[r * 6 + 2 * p], s * Wi[r * 6 + 2 * p + 1]);
            W.wh[q][p] = pack2(s * Wh[r * 6 + 2 * p], s * Wh[r * 6 + 2 * p + 1]);
        }
        W.b[q] = pack2(s * (bi[r] + bh[r]), 0.f);
    }

    const float* xb = x + (size_t)b * TT * 6;

    float h = 0.f, c = 0.f;

    u64 A[12], B[12];                // x double buffer: 4 timesteps per block
    loadblk(xb, 0, B);
    loadblk(xb, 1, A);

    steps4<true>(W, isL1, rbase, gbase, B, h, c);   // block 0 (zero-fix at step 0)

#pragma unroll 1
    for (int m = 1; m < 511; m += 2) {
        loadblk(xb, m + 1, B);
        steps4<false>(W, isL1, rbase, gbase, A, h, c);   // block m
        loadblk(xb, m + 2, A);
        steps4<false>(W, isL1, rbase, gbase, B, h, c);   // block m+1
    }
    steps4<false>(W, isL1, rbase, gbase, A, h, c);       // block 511

    // Epilogue iteration 2048: layer 1 consumes h0(2047); L0 input zero (discarded).
    {
        u64 z[3] = {0ull, 0ull, 0ull};
        iter<false>(W, isL1, rbase, gbase, z, h, c);
    }

    // Gather final layer-1 h (lanes gbase+8+k) and softmax.
    float hv[6];
#pragma unroll
    for (int k = 0; k < 6; ++k)
        hv[k] = __shfl_sync(0xffffffffu, h, gbase + 8 + k);
    float m = hv[0];
#pragma unroll
    for (int k = 1; k < 6; ++k) m = fmaxf(m, hv[k]);
    float s = 0.f, ev[6];
#pragma unroll
    for (int k = 0; k < 6; ++k) { ev[k] = __expf(hv[k] - m); s += ev[k]; }
    if (isL1 && j < 6)
        out[(size_t)b * 6 + j] = __fdividef(ev[j], s);
}

extern "C" void kernel_launch(void* const* d_in, const int* in_sizes, int n_in,
                              void* d_out, int out_size) {
    (void)in_sizes; (void)n_in; (void)out_size;
    const float* x   = (const float*)d_in[0];
    const float* Wi0 = (const float*)d_in[1];
    const float* Wh0 = (const float*)d_in[2];
    const float* bi0 = (const float*)d_in[3];
    const float* bh0 = (const float*)d_in[4];
    const float* Wi1 = (const float*)d_in[5];
    const float* Wh1 = (const float*)d_in[6];
    const float* bi1 = (const float*)d_in[7];
    const float* bh1 = (const float*)d_in[8];
    float* out = (float*)d_out;

    // 2048 batches * 16 lanes = 32768 threads = 128 blocks x 256 threads:
    // 1 block/SM on 128 SMs, uniform 2 warps/SMSP.
    stacked_lstm_kernel<<<128, 256>>>(x, Wi0, Wh0, bi0, bh0, Wi1, Wh1, bi1, bh1, out);
}